// round 10
// baseline (speedup 1.0000x reference)
#include <cuda_runtime.h>

#define N_NODES 100000
#define N_EDGES 3200000
#define IN_DIM 64
#define HID_DIM 128
#define OUT_DIM 2
#define IN_VEC (IN_DIM / 4)       // 16 float4 per node row
#define HID_VEC (HID_DIM / 4)     // 32

#define SCAN_CHUNK 1024
#define N_SCAN_BLOCKS ((N_NODES + SCAN_CHUNK - 1) / SCAN_CHUNK)   // 98

// Scratch (device globals: allocation-free rule)
__device__ __align__(16) int    g_cnt[N_NODES];
__device__ __align__(16) int    g_start[N_NODES];
__device__ __align__(16) int    g_cur[N_NODES];
__device__ __align__(16) float  g_dinv[N_NODES];
__device__ __align__(16) int    g_bsum[N_SCAN_BLOCKS];
__device__ __align__(16) float2 g_entry[N_EDGES];          // {src bits, norm} 25.6 MB
__device__ __align__(16) float4 g_agg[N_NODES * IN_VEC];   // 25.6 MB

// Packed f32x2 helpers (SASS FFMA2 — 2 fp32 MACs per instruction)
__device__ __forceinline__ unsigned long long pack2(float lo, float hi) {
    unsigned long long r;
    asm("mov.b64 %0, {%1, %2};" : "=l"(r) : "f"(lo), "f"(hi));
    return r;
}
__device__ __forceinline__ unsigned long long fma2(unsigned long long a,
                                                   unsigned long long b,
                                                   unsigned long long c) {
    unsigned long long d;
    asm("fma.rn.f32x2 %0, %1, %2, %3;" : "=l"(d) : "l"(a), "l"(b), "l"(c));
    return d;
}
__device__ __forceinline__ void unpack2(unsigned long long v, float& lo, float& hi) {
    asm("mov.b64 {%0, %1}, %2;" : "=f"(lo), "=f"(hi) : "l"(v));
}

// ---------------------------------------------------------------------------
__global__ void k_zero() {
    int i = blockIdx.x * blockDim.x + threadIdx.x;
    if (i < N_NODES) g_cnt[i] = 0;
}

// In-degree histogram (int reductions)
__global__ void k_count(const int* __restrict__ ei) {
    int i = blockIdx.x * blockDim.x + threadIdx.x;
    if (i < N_EDGES) {
        int d = ei[N_EDGES + i];
        if ((unsigned)d < N_NODES) atomicAdd(&g_cnt[d], 1);
    }
}

// Scan pass 1: per-block (1024 elems) exclusive scan of g_cnt into g_start,
// block totals to g_bsum. Also dinv = rsqrt(cnt+1) (self-loop incl).
__global__ __launch_bounds__(256)
void k_scan1() {
    __shared__ int s_sum[256];
    int b = blockIdx.x, t = threadIdx.x;
    int base = b * SCAN_CHUNK + t * 4;

    int c0 = 0, c1 = 0, c2 = 0, c3 = 0;
    if (base + 3 < N_NODES) {
        int4 c = *(const int4*)&g_cnt[base];
        c0 = c.x; c1 = c.y; c2 = c.z; c3 = c.w;
    } else {
        if (base + 0 < N_NODES) c0 = g_cnt[base + 0];
        if (base + 1 < N_NODES) c1 = g_cnt[base + 1];
        if (base + 2 < N_NODES) c2 = g_cnt[base + 2];
    }
    int s0 = c0, s1 = s0 + c1, s2 = s1 + c2, s3 = s2 + c3;
    s_sum[t] = s3;
    __syncthreads();
#pragma unroll
    for (int off = 1; off < 256; off <<= 1) {
        int v = 0;
        if (t >= off) v = s_sum[t - off];
        __syncthreads();
        if (t >= off) s_sum[t] += v;
        __syncthreads();
    }
    int excl = (t > 0) ? s_sum[t - 1] : 0;
    if (base + 0 < N_NODES) { g_start[base + 0] = excl;       g_dinv[base + 0] = rsqrtf((float)c0 + 1.0f); }
    if (base + 1 < N_NODES) { g_start[base + 1] = excl + s0;  g_dinv[base + 1] = rsqrtf((float)c1 + 1.0f); }
    if (base + 2 < N_NODES) { g_start[base + 2] = excl + s1;  g_dinv[base + 2] = rsqrtf((float)c2 + 1.0f); }
    if (base + 3 < N_NODES) { g_start[base + 3] = excl + s2;  g_dinv[base + 3] = rsqrtf((float)c3 + 1.0f); }
    if (t == 255) g_bsum[b] = s_sum[255];
}

// Scan pass 2: exclusive scan of the 98 block sums (single block)
__global__ __launch_bounds__(128)
void k_scan2() {
    __shared__ int s[128];
    int t = threadIdx.x;
    s[t] = (t < N_SCAN_BLOCKS) ? g_bsum[t] : 0;
    __syncthreads();
#pragma unroll
    for (int off = 1; off < 128; off <<= 1) {
        int v = 0;
        if (t >= off) v = s[t - off];
        __syncthreads();
        if (t >= off) s[t] += v;
        __syncthreads();
    }
    if (t < N_SCAN_BLOCKS) g_bsum[t] = (t > 0) ? s[t - 1] : 0;
}

// Scan pass 3: add block offsets; init write cursors
__global__ void k_scan3() {
    int i = blockIdx.x * blockDim.x + threadIdx.x;
    if (i < N_NODES) {
        int v = g_start[i] + g_bsum[i >> 10];
        g_start[i] = v;
        g_cur[i] = v;
    }
}

// Counting-sort fill: per-dst edge lists of packed {src, norm}
__global__ void k_scatter(const int* __restrict__ ei) {
    int i = blockIdx.x * blockDim.x + threadIdx.x;
    if (i < N_EDGES) {
        int s = ei[i];
        int t = ei[N_EDGES + i];
        if ((unsigned)s >= N_NODES || (unsigned)t >= N_NODES) return;
        float norm = g_dinv[s] * g_dinv[t];
        int slot = atomicAdd(&g_cur[t], 1);
        if ((unsigned)slot < N_EDGES)                 // clamp: corrupt -> wrong, not hang
            g_entry[slot] = make_float2(__int_as_float(s), norm);
    }
}

// Aggregate: 16 threads per node, register accumulation, ZERO float atomics.
// agg[node] = x[node]*dinv^2 + sum_{in-edges} x[src]*norm.  MLP=4 gathers.
__global__ __launch_bounds__(256)
void k_agg(const float4* __restrict__ x4) {
    int gi = blockIdx.x * blockDim.x + threadIdx.x;
    if (gi >= N_NODES * IN_VEC) return;
    int node = gi >> 4;
    int lane = gi & 15;

    float di = g_dinv[node];
    float sl = di * di;
    float4 acc = x4[node * IN_VEC + lane];
    acc.x *= sl; acc.y *= sl; acc.z *= sl; acc.w *= sl;

    // Hard-clamped bounds: any upstream corruption ends finitely.
    int j = g_start[node];
    if (j < 0) j = 0;
    int cnt = g_cnt[node];
    if (cnt < 0) cnt = 0;
    long long e64 = (long long)j + cnt;
    int end = (e64 > N_EDGES) ? N_EDGES : (int)e64;

    // 4-wide unroll: 4 independent gathers in flight
    for (; j + 3 < end; j += 4) {
        float2 en0 = g_entry[j + 0];
        float2 en1 = g_entry[j + 1];
        float2 en2 = g_entry[j + 2];
        float2 en3 = g_entry[j + 3];
        int s0 = __float_as_int(en0.x);
        int s1 = __float_as_int(en1.x);
        int s2 = __float_as_int(en2.x);
        int s3 = __float_as_int(en3.x);
        float4 v0 = __ldg(&x4[((unsigned)s0 < N_NODES ? s0 : 0) * IN_VEC + lane]);
        float4 v1 = __ldg(&x4[((unsigned)s1 < N_NODES ? s1 : 0) * IN_VEC + lane]);
        float4 v2 = __ldg(&x4[((unsigned)s2 < N_NODES ? s2 : 0) * IN_VEC + lane]);
        float4 v3 = __ldg(&x4[((unsigned)s3 < N_NODES ? s3 : 0) * IN_VEC + lane]);
        acc.x = fmaf(v0.x, en0.y, acc.x); acc.y = fmaf(v0.y, en0.y, acc.y);
        acc.z = fmaf(v0.z, en0.y, acc.z); acc.w = fmaf(v0.w, en0.y, acc.w);
        acc.x = fmaf(v1.x, en1.y, acc.x); acc.y = fmaf(v1.y, en1.y, acc.y);
        acc.z = fmaf(v1.z, en1.y, acc.z); acc.w = fmaf(v1.w, en1.y, acc.w);
        acc.x = fmaf(v2.x, en2.y, acc.x); acc.y = fmaf(v2.y, en2.y, acc.y);
        acc.z = fmaf(v2.z, en2.y, acc.z); acc.w = fmaf(v2.w, en2.y, acc.w);
        acc.x = fmaf(v3.x, en3.y, acc.x); acc.y = fmaf(v3.y, en3.y, acc.y);
        acc.z = fmaf(v3.z, en3.y, acc.z); acc.w = fmaf(v3.w, en3.y, acc.w);
    }
    for (; j < end; j++) {
        float2 en = g_entry[j];
        int s0 = __float_as_int(en.x);
        if ((unsigned)s0 < N_NODES) {
            float4 v = __ldg(&x4[s0 * IN_VEC + lane]);
            acc.x = fmaf(v.x, en.y, acc.x);
            acc.y = fmaf(v.y, en.y, acc.y);
            acc.z = fmaf(v.z, en.y, acc.z);
            acc.w = fmaf(v.w, en.y, acc.w);
        }
    }
    g_agg[node * IN_VEC + lane] = acc;
}

// Head: out = relu(agg @ W_gcn + b_gcn) @ W_lin + b_lin
// One thread/node; FFMA2 packed math (fma.rn.f32x2): 2 MACs/instr.
// Per-output accumulation order identical to scalar version -> bitwise same.
__global__ __launch_bounds__(128)
void k_head(const float4* __restrict__ Wg4,
            const float* __restrict__ bg,
            const float* __restrict__ Wl,
            const float* __restrict__ bl,
            float2* __restrict__ out) {
    __shared__ float4 sW[IN_DIM * HID_VEC];   // 32 KB, [k][jq] quads
    __shared__ float  sWl[HID_DIM * 2];
    __shared__ float  sbg[HID_DIM];

    int tid = threadIdx.x;
    for (int i = tid; i < IN_DIM * HID_VEC; i += blockDim.x) sW[i] = Wg4[i];
    for (int i = tid; i < HID_DIM * 2; i += blockDim.x) sWl[i] = Wl[i];
    for (int i = tid; i < HID_DIM; i += blockDim.x) sbg[i] = bg[i];
    __syncthreads();

    int node = blockIdx.x * blockDim.x + tid;
    if (node >= N_NODES) return;

    float a[IN_DIM];
    const float4* arow = &g_agg[node * IN_VEC];
#pragma unroll
    for (int k = 0; k < IN_VEC; k++) {
        float4 v = arow[k];
        a[4*k+0] = v.x; a[4*k+1] = v.y; a[4*k+2] = v.z; a[4*k+3] = v.w;
    }

    float o0 = bl[0], o1 = bl[1];
#pragma unroll 1
    for (int h = 0; h < 2; h++) {                 // two tiles of 16 jq-quads
        int jq0 = h * 16;
        unsigned long long acc[32];               // 16 quads x 2 f32x2
#pragma unroll
        for (int q = 0; q < 16; q++) {
            int j = 4 * (jq0 + q);
            acc[2*q+0] = pack2(sbg[j+0], sbg[j+1]);
            acc[2*q+1] = pack2(sbg[j+2], sbg[j+3]);
        }
#pragma unroll
        for (int k = 0; k < IN_DIM; k++) {
            unsigned long long a2 = pack2(a[k], a[k]);   // 1 pack / 32 FFMA2
            const ulonglong2* wrow =
                (const ulonglong2*)&sW[k * HID_VEC + jq0];
#pragma unroll
            for (int q = 0; q < 16; q++) {
                ulonglong2 w = wrow[q];           // LDS.128 -> two 64b pairs
                acc[2*q+0] = fma2(a2, w.x, acc[2*q+0]);
                acc[2*q+1] = fma2(a2, w.y, acc[2*q+1]);
            }
        }
        // epilogue: unpack, relu, linear head
#pragma unroll
        for (int q = 0; q < 16; q++) {
            float h0, h1, h2, h3;
            unpack2(acc[2*q+0], h0, h1);
            unpack2(acc[2*q+1], h2, h3);
            h0 = fmaxf(h0, 0.0f); h1 = fmaxf(h1, 0.0f);
            h2 = fmaxf(h2, 0.0f); h3 = fmaxf(h3, 0.0f);
            int j = 4 * (jq0 + q);
            o0 = fmaf(h0, sWl[2*(j+0)+0], o0);
            o1 = fmaf(h0, sWl[2*(j+0)+1], o1);
            o0 = fmaf(h1, sWl[2*(j+1)+0], o0);
            o1 = fmaf(h1, sWl[2*(j+1)+1], o1);
            o0 = fmaf(h2, sWl[2*(j+2)+0], o0);
            o1 = fmaf(h2, sWl[2*(j+2)+1], o1);
            o0 = fmaf(h3, sWl[2*(j+3)+0], o0);
            o1 = fmaf(h3, sWl[2*(j+3)+1], o1);
        }
    }
    out[node] = make_float2(o0, o1);
}

// ---------------------------------------------------------------------------
extern "C" void kernel_launch(void* const* d_in, const int* in_sizes, int n_in,
                              void* d_out, int out_size) {
    const float* x  = (const float*)d_in[0];
    const int*   ei = (const int*)d_in[1];     // int32 (JAX default x64 off)
    const float* Wg = (const float*)d_in[2];
    const float* bg = (const float*)d_in[3];
    const float* Wl = (const float*)d_in[4];
    const float* bl = (const float*)d_in[5];
    float2*      out = (float2*)d_out;

    const float4* x4  = (const float4*)x;
    const float4* Wg4 = (const float4*)Wg;

    k_zero   <<<(N_NODES + 255) / 256, 256>>>();
    k_count  <<<(N_EDGES + 255) / 256, 256>>>(ei);
    k_scan1  <<<N_SCAN_BLOCKS, 256>>>();
    k_scan2  <<<1, 128>>>();
    k_scan3  <<<(N_NODES + 255) / 256, 256>>>();
    k_scatter<<<(N_EDGES + 255) / 256, 256>>>(ei);
    k_agg    <<<(N_NODES * IN_VEC + 255) / 256, 256>>>(x4);
    k_head   <<<(N_NODES + 127) / 128, 128>>>(Wg4, bg, Wl, bl, out);
}

// round 12
// speedup vs baseline: 1.0291x; 1.0291x over previous
#include <cuda_runtime.h>

#define N_NODES 100000
#define N_EDGES 3200000
#define IN_DIM 64
#define HID_DIM 128
#define OUT_DIM 2
#define IN_VEC (IN_DIM / 4)       // 16 float4 per node row
#define HID_VEC (HID_DIM / 4)     // 32

#define SCAN_CHUNK 1024
#define N_SCAN_BLOCKS ((N_NODES + SCAN_CHUNK - 1) / SCAN_CHUNK)   // 98

// Scratch (device globals: allocation-free rule)
__device__ __align__(16) int    g_cnt[N_NODES];
__device__ __align__(16) int    g_start[N_NODES];
__device__ __align__(16) int    g_cur[N_NODES];
__device__ __align__(16) float  g_dinv[N_NODES];
__device__ __align__(16) int    g_bsum[N_SCAN_BLOCKS];
__device__ __align__(16) float2 g_entry[N_EDGES];          // {src bits, norm} 25.6 MB
__device__ __align__(16) float4 g_agg[N_NODES * IN_VEC];   // 25.6 MB

// Packed f32x2 helpers (SASS FFMA2 — 2 fp32 MACs per instruction)
__device__ __forceinline__ unsigned long long pack2(float lo, float hi) {
    unsigned long long r;
    asm("mov.b64 %0, {%1, %2};" : "=l"(r) : "f"(lo), "f"(hi));
    return r;
}
__device__ __forceinline__ unsigned long long fma2(unsigned long long a,
                                                   unsigned long long b,
                                                   unsigned long long c) {
    unsigned long long d;
    asm("fma.rn.f32x2 %0, %1, %2, %3;" : "=l"(d) : "l"(a), "l"(b), "l"(c));
    return d;
}
__device__ __forceinline__ void unpack2(unsigned long long v, float& lo, float& hi) {
    asm("mov.b64 {%0, %1}, %2;" : "=f"(lo), "=f"(hi) : "l"(v));
}

// ---------------------------------------------------------------------------
__global__ void k_zero() {
    int i = blockIdx.x * blockDim.x + threadIdx.x;
    if (i < N_NODES) g_cnt[i] = 0;
}

// In-degree histogram (int reductions)
__global__ void k_count(const int* __restrict__ ei) {
    int i = blockIdx.x * blockDim.x + threadIdx.x;
    if (i < N_EDGES) {
        int d = ei[N_EDGES + i];
        if ((unsigned)d < N_NODES) atomicAdd(&g_cnt[d], 1);
    }
}

// Scan pass 1: per-block (1024 elems) exclusive scan of g_cnt into g_start,
// block totals to g_bsum. Also dinv = rsqrt(cnt+1) (self-loop incl).
__global__ __launch_bounds__(256)
void k_scan1() {
    __shared__ int s_sum[256];
    int b = blockIdx.x, t = threadIdx.x;
    int base = b * SCAN_CHUNK + t * 4;

    int c0 = 0, c1 = 0, c2 = 0, c3 = 0;
    if (base + 3 < N_NODES) {
        int4 c = *(const int4*)&g_cnt[base];
        c0 = c.x; c1 = c.y; c2 = c.z; c3 = c.w;
    } else {
        if (base + 0 < N_NODES) c0 = g_cnt[base + 0];
        if (base + 1 < N_NODES) c1 = g_cnt[base + 1];
        if (base + 2 < N_NODES) c2 = g_cnt[base + 2];
    }
    int s0 = c0, s1 = s0 + c1, s2 = s1 + c2, s3 = s2 + c3;
    s_sum[t] = s3;
    __syncthreads();
#pragma unroll
    for (int off = 1; off < 256; off <<= 1) {
        int v = 0;
        if (t >= off) v = s_sum[t - off];
        __syncthreads();
        if (t >= off) s_sum[t] += v;
        __syncthreads();
    }
    int excl = (t > 0) ? s_sum[t - 1] : 0;
    if (base + 0 < N_NODES) { g_start[base + 0] = excl;       g_dinv[base + 0] = rsqrtf((float)c0 + 1.0f); }
    if (base + 1 < N_NODES) { g_start[base + 1] = excl + s0;  g_dinv[base + 1] = rsqrtf((float)c1 + 1.0f); }
    if (base + 2 < N_NODES) { g_start[base + 2] = excl + s1;  g_dinv[base + 2] = rsqrtf((float)c2 + 1.0f); }
    if (base + 3 < N_NODES) { g_start[base + 3] = excl + s2;  g_dinv[base + 3] = rsqrtf((float)c3 + 1.0f); }
    if (t == 255) g_bsum[b] = s_sum[255];
}

// Scan pass 2: exclusive scan of the 98 block sums (single block)
__global__ __launch_bounds__(128)
void k_scan2() {
    __shared__ int s[128];
    int t = threadIdx.x;
    s[t] = (t < N_SCAN_BLOCKS) ? g_bsum[t] : 0;
    __syncthreads();
#pragma unroll
    for (int off = 1; off < 128; off <<= 1) {
        int v = 0;
        if (t >= off) v = s[t - off];
        __syncthreads();
        if (t >= off) s[t] += v;
        __syncthreads();
    }
    if (t < N_SCAN_BLOCKS) g_bsum[t] = (t > 0) ? s[t - 1] : 0;
}

// Scan pass 3: add block offsets; init write cursors
__global__ void k_scan3() {
    int i = blockIdx.x * blockDim.x + threadIdx.x;
    if (i < N_NODES) {
        int v = g_start[i] + g_bsum[i >> 10];
        g_start[i] = v;
        g_cur[i] = v;
    }
}

// Counting-sort fill: per-dst edge lists of packed {src, norm}
__global__ void k_scatter(const int* __restrict__ ei) {
    int i = blockIdx.x * blockDim.x + threadIdx.x;
    if (i < N_EDGES) {
        int s = ei[i];
        int t = ei[N_EDGES + i];
        if ((unsigned)s >= N_NODES || (unsigned)t >= N_NODES) return;
        float norm = g_dinv[s] * g_dinv[t];
        int slot = atomicAdd(&g_cur[t], 1);
        if ((unsigned)slot < N_EDGES)                 // clamp: corrupt -> wrong, not hang
            g_entry[slot] = make_float2(__int_as_float(s), norm);
    }
}

// Aggregate: 16 threads per node, register accumulation, ZERO float atomics.
// (exact R8 version: 2-wide unroll with early-skip guards)
__global__ __launch_bounds__(256)
void k_agg(const float4* __restrict__ x4) {
    int gi = blockIdx.x * blockDim.x + threadIdx.x;
    if (gi >= N_NODES * IN_VEC) return;
    int node = gi >> 4;
    int lane = gi & 15;

    float di = g_dinv[node];
    float sl = di * di;
    float4 acc = x4[node * IN_VEC + lane];
    acc.x *= sl; acc.y *= sl; acc.z *= sl; acc.w *= sl;

    // Hard-clamped bounds: any upstream corruption ends finitely.
    int j = g_start[node];
    if (j < 0) j = 0;
    int cnt = g_cnt[node];
    if (cnt < 0) cnt = 0;
    long long e64 = (long long)j + cnt;
    int end = (e64 > N_EDGES) ? N_EDGES : (int)e64;

    for (; j + 1 < end; j += 2) {
        float2 en0 = g_entry[j];
        float2 en1 = g_entry[j + 1];
        int s0 = __float_as_int(en0.x);
        int s1 = __float_as_int(en1.x);
        if ((unsigned)s0 < N_NODES) {
            float4 v = __ldg(&x4[s0 * IN_VEC + lane]);
            acc.x = fmaf(v.x, en0.y, acc.x);
            acc.y = fmaf(v.y, en0.y, acc.y);
            acc.z = fmaf(v.z, en0.y, acc.z);
            acc.w = fmaf(v.w, en0.y, acc.w);
        }
        if ((unsigned)s1 < N_NODES) {
            float4 v = __ldg(&x4[s1 * IN_VEC + lane]);
            acc.x = fmaf(v.x, en1.y, acc.x);
            acc.y = fmaf(v.y, en1.y, acc.y);
            acc.z = fmaf(v.z, en1.y, acc.z);
            acc.w = fmaf(v.w, en1.y, acc.w);
        }
    }
    if (j < end) {
        float2 en = g_entry[j];
        int s0 = __float_as_int(en.x);
        if ((unsigned)s0 < N_NODES) {
            float4 v = __ldg(&x4[s0 * IN_VEC + lane]);
            acc.x = fmaf(v.x, en.y, acc.x);
            acc.y = fmaf(v.y, en.y, acc.y);
            acc.z = fmaf(v.z, en.y, acc.z);
            acc.w = fmaf(v.w, en.y, acc.w);
        }
    }
    g_agg[node * IN_VEC + lane] = acc;
}

// Head: out = relu(agg @ W_gcn + b_gcn) @ W_lin + b_lin
// FFMA2 packed math, LOW register pressure: 4 tiles of 8 jq-quads
// (acc[16] u64 = 32 regs live per tile). Per-output accumulation order
// identical to scalar version.
__global__ __launch_bounds__(128)
void k_head(const float4* __restrict__ Wg4,
            const float* __restrict__ bg,
            const float* __restrict__ Wl,
            const float* __restrict__ bl,
            float2* __restrict__ out) {
    __shared__ float4 sW[IN_DIM * HID_VEC];   // 32 KB, [k][jq] quads
    __shared__ float  sWl[HID_DIM * 2];
    __shared__ float  sbg[HID_DIM];

    int tid = threadIdx.x;
    for (int i = tid; i < IN_DIM * HID_VEC; i += blockDim.x) sW[i] = Wg4[i];
    for (int i = tid; i < HID_DIM * 2; i += blockDim.x) sWl[i] = Wl[i];
    for (int i = tid; i < HID_DIM; i += blockDim.x) sbg[i] = bg[i];
    __syncthreads();

    int node = blockIdx.x * blockDim.x + tid;
    if (node >= N_NODES) return;

    float a[IN_DIM];
    const float4* arow = &g_agg[node * IN_VEC];
#pragma unroll
    for (int k = 0; k < IN_VEC; k++) {
        float4 v = arow[k];
        a[4*k+0] = v.x; a[4*k+1] = v.y; a[4*k+2] = v.z; a[4*k+3] = v.w;
    }

    float o0 = bl[0], o1 = bl[1];
#pragma unroll 1
    for (int h = 0; h < 4; h++) {                 // 4 tiles of 8 jq-quads
        int jq0 = h * 8;
        unsigned long long acc[16];               // 8 quads x 2 f32x2 = 32 regs
#pragma unroll
        for (int q = 0; q < 8; q++) {
            int j = 4 * (jq0 + q);
            acc[2*q+0] = pack2(sbg[j+0], sbg[j+1]);
            acc[2*q+1] = pack2(sbg[j+2], sbg[j+3]);
        }
#pragma unroll
        for (int k = 0; k < IN_DIM; k++) {
            unsigned long long a2 = pack2(a[k], a[k]);   // 1 pack / 16 FFMA2
            const ulonglong2* wrow =
                (const ulonglong2*)&sW[k * HID_VEC + jq0];
#pragma unroll
            for (int q = 0; q < 8; q++) {
                ulonglong2 w = wrow[q];           // LDS.128 -> two 64b pairs
                acc[2*q+0] = fma2(a2, w.x, acc[2*q+0]);
                acc[2*q+1] = fma2(a2, w.y, acc[2*q+1]);
            }
        }
        // epilogue: unpack, relu, linear head
#pragma unroll
        for (int q = 0; q < 8; q++) {
            float h0, h1, h2, h3;
            unpack2(acc[2*q+0], h0, h1);
            unpack2(acc[2*q+1], h2, h3);
            h0 = fmaxf(h0, 0.0f); h1 = fmaxf(h1, 0.0f);
            h2 = fmaxf(h2, 0.0f); h3 = fmaxf(h3, 0.0f);
            int j = 4 * (jq0 + q);
            o0 = fmaf(h0, sWl[2*(j+0)+0], o0);
            o1 = fmaf(h0, sWl[2*(j+0)+1], o1);
            o0 = fmaf(h1, sWl[2*(j+1)+0], o0);
            o1 = fmaf(h1, sWl[2*(j+1)+1], o1);
            o0 = fmaf(h2, sWl[2*(j+2)+0], o0);
            o1 = fmaf(h2, sWl[2*(j+2)+1], o1);
            o0 = fmaf(h3, sWl[2*(j+3)+0], o0);
            o1 = fmaf(h3, sWl[2*(j+3)+1], o1);
        }
    }
    out[node] = make_float2(o0, o1);
}

// ---------------------------------------------------------------------------
extern "C" void kernel_launch(void* const* d_in, const int* in_sizes, int n_in,
                              void* d_out, int out_size) {
    const float* x  = (const float*)d_in[0];
    const int*   ei = (const int*)d_in[1];     // int32 (JAX default x64 off)
    const float* Wg = (const float*)d_in[2];
    const float* bg = (const float*)d_in[3];
    const float* Wl = (const float*)d_in[4];
    const float* bl = (const float*)d_in[5];
    float2*      out = (float2*)d_out;

    const float4* x4  = (const float4*)x;
    const float4* Wg4 = (const float4*)Wg;

    k_zero   <<<(N_NODES + 255) / 256, 256>>>();
    k_count  <<<(N_EDGES + 255) / 256, 256>>>(ei);
    k_scan1  <<<N_SCAN_BLOCKS, 256>>>();
    k_scan2  <<<1, 128>>>();
    k_scan3  <<<(N_NODES + 255) / 256, 256>>>();
    k_scatter<<<(N_EDGES + 255) / 256, 256>>>(ei);
    k_agg    <<<(N_NODES * IN_VEC + 255) / 256, 256>>>(x4);
    k_head   <<<(N_NODES + 127) / 128, 128>>>(Wg4, bg, Wl, bl, out);
}

// round 13
// speedup vs baseline: 1.0385x; 1.0092x over previous
#include <cuda_runtime.h>

#define N_NODES 100000
#define N_EDGES 3200000
#define IN_DIM 64
#define HID_DIM 128
#define OUT_DIM 2
#define IN_VEC (IN_DIM / 4)       // 16 float4 per node row
#define HID_VEC (HID_DIM / 4)     // 32

#define SCAN_CHUNK 1024
#define N_SCAN_BLOCKS ((N_NODES + SCAN_CHUNK - 1) / SCAN_CHUNK)   // 98

// Scratch (device globals: allocation-free rule)
__device__ __align__(16) int    g_cnt[N_NODES];
__device__ __align__(16) int    g_start[N_NODES];
__device__ __align__(16) int    g_cur[N_NODES];
__device__ __align__(16) float  g_dinv[N_NODES];
__device__ __align__(16) int    g_bsum[N_SCAN_BLOCKS];
__device__ __align__(16) float2 g_entry[N_EDGES];          // {src bits, norm} 25.6 MB
__device__ __align__(16) float4 g_agg[N_NODES * IN_VEC];   // 25.6 MB

// ---------------------------------------------------------------------------
__global__ void k_zero() {
    int i = blockIdx.x * blockDim.x + threadIdx.x;
    if (i < N_NODES) g_cnt[i] = 0;
}

// In-degree histogram (int reductions)
__global__ void k_count(const int* __restrict__ ei) {
    int i = blockIdx.x * blockDim.x + threadIdx.x;
    if (i < N_EDGES) {
        int d = ei[N_EDGES + i];
        if ((unsigned)d < N_NODES) atomicAdd(&g_cnt[d], 1);
    }
}

// Scan pass 1: per-block (1024 elems) exclusive scan of g_cnt into g_start,
// block totals to g_bsum. Also dinv = rsqrt(cnt+1) (self-loop incl).
__global__ __launch_bounds__(256)
void k_scan1() {
    __shared__ int s_sum[256];
    int b = blockIdx.x, t = threadIdx.x;
    int base = b * SCAN_CHUNK + t * 4;

    int c0 = 0, c1 = 0, c2 = 0, c3 = 0;
    if (base + 3 < N_NODES) {
        int4 c = *(const int4*)&g_cnt[base];
        c0 = c.x; c1 = c.y; c2 = c.z; c3 = c.w;
    } else {
        if (base + 0 < N_NODES) c0 = g_cnt[base + 0];
        if (base + 1 < N_NODES) c1 = g_cnt[base + 1];
        if (base + 2 < N_NODES) c2 = g_cnt[base + 2];
    }
    int s0 = c0, s1 = s0 + c1, s2 = s1 + c2, s3 = s2 + c3;
    s_sum[t] = s3;
    __syncthreads();
#pragma unroll
    for (int off = 1; off < 256; off <<= 1) {
        int v = 0;
        if (t >= off) v = s_sum[t - off];
        __syncthreads();
        if (t >= off) s_sum[t] += v;
        __syncthreads();
    }
    int excl = (t > 0) ? s_sum[t - 1] : 0;
    if (base + 0 < N_NODES) { g_start[base + 0] = excl;       g_dinv[base + 0] = rsqrtf((float)c0 + 1.0f); }
    if (base + 1 < N_NODES) { g_start[base + 1] = excl + s0;  g_dinv[base + 1] = rsqrtf((float)c1 + 1.0f); }
    if (base + 2 < N_NODES) { g_start[base + 2] = excl + s1;  g_dinv[base + 2] = rsqrtf((float)c2 + 1.0f); }
    if (base + 3 < N_NODES) { g_start[base + 3] = excl + s2;  g_dinv[base + 3] = rsqrtf((float)c3 + 1.0f); }
    if (t == 255) g_bsum[b] = s_sum[255];
}

// Scan pass 2: exclusive scan of the 98 block sums (single block)
__global__ __launch_bounds__(128)
void k_scan2() {
    __shared__ int s[128];
    int t = threadIdx.x;
    s[t] = (t < N_SCAN_BLOCKS) ? g_bsum[t] : 0;
    __syncthreads();
#pragma unroll
    for (int off = 1; off < 128; off <<= 1) {
        int v = 0;
        if (t >= off) v = s[t - off];
        __syncthreads();
        if (t >= off) s[t] += v;
        __syncthreads();
    }
    if (t < N_SCAN_BLOCKS) g_bsum[t] = (t > 0) ? s[t - 1] : 0;
}

// Scan pass 3: add block offsets; init write cursors
__global__ void k_scan3() {
    int i = blockIdx.x * blockDim.x + threadIdx.x;
    if (i < N_NODES) {
        int v = g_start[i] + g_bsum[i >> 10];
        g_start[i] = v;
        g_cur[i] = v;
    }
}

// Counting-sort fill: per-dst edge lists of packed {src, norm}
__global__ void k_scatter(const int* __restrict__ ei) {
    int i = blockIdx.x * blockDim.x + threadIdx.x;
    if (i < N_EDGES) {
        int s = ei[i];
        int t = ei[N_EDGES + i];
        if ((unsigned)s >= N_NODES || (unsigned)t >= N_NODES) return;
        float norm = g_dinv[s] * g_dinv[t];
        int slot = atomicAdd(&g_cur[t], 1);
        if ((unsigned)slot < N_EDGES)                 // clamp: corrupt -> wrong, not hang
            g_entry[slot] = make_float2(__int_as_float(s), norm);
    }
}

// Aggregate: ONE WARP per node. Half-warp 0 handles even edges, half-warp 1
// odd edges -> uniform trip count (no cross-node divergence). 2-unrolled per
// half (4 gathers in flight per warp). Final shfl.bfly(16) combine.
__global__ __launch_bounds__(256)
void k_agg(const float4* __restrict__ x4) {
    int warp = (blockIdx.x * blockDim.x + threadIdx.x) >> 5;
    if (warp >= N_NODES) return;
    int node = warp;
    int lane = threadIdx.x & 31;
    int half = lane >> 4;        // 0 or 1
    int l16  = lane & 15;        // float4 column within the node row

    float di = g_dinv[node];
    float4 acc = make_float4(0.f, 0.f, 0.f, 0.f);
    if (half == 0) {             // self-loop contribution once
        float sl = di * di;
        float4 v = x4[node * IN_VEC + l16];
        acc.x = v.x * sl; acc.y = v.y * sl; acc.z = v.z * sl; acc.w = v.w * sl;
    }

    // Hard-clamped bounds: any upstream corruption ends finitely.
    int jstart = g_start[node];
    if (jstart < 0) jstart = 0;
    int cnt = g_cnt[node];
    if (cnt < 0) cnt = 0;
    long long e64 = (long long)jstart + cnt;
    int end = (e64 > N_EDGES) ? N_EDGES : (int)e64;

    int j = jstart + half;       // this half's strided list: j, j+2, j+4, ...
    for (; j + 2 < end; j += 4) {
        float2 en0 = g_entry[j];
        float2 en1 = g_entry[j + 2];
        int s0 = __float_as_int(en0.x);
        int s1 = __float_as_int(en1.x);
        float w0 = ((unsigned)s0 < N_NODES) ? en0.y : 0.0f;
        float w1 = ((unsigned)s1 < N_NODES) ? en1.y : 0.0f;
        float4 v0 = __ldg(&x4[((unsigned)s0 < N_NODES ? s0 : 0) * IN_VEC + l16]);
        float4 v1 = __ldg(&x4[((unsigned)s1 < N_NODES ? s1 : 0) * IN_VEC + l16]);
        acc.x = fmaf(v0.x, w0, acc.x); acc.y = fmaf(v0.y, w0, acc.y);
        acc.z = fmaf(v0.z, w0, acc.z); acc.w = fmaf(v0.w, w0, acc.w);
        acc.x = fmaf(v1.x, w1, acc.x); acc.y = fmaf(v1.y, w1, acc.y);
        acc.z = fmaf(v1.z, w1, acc.z); acc.w = fmaf(v1.w, w1, acc.w);
    }
    if (j < end) {
        float2 en = g_entry[j];
        int s0 = __float_as_int(en.x);
        float w0 = ((unsigned)s0 < N_NODES) ? en.y : 0.0f;
        float4 v = __ldg(&x4[((unsigned)s0 < N_NODES ? s0 : 0) * IN_VEC + l16]);
        acc.x = fmaf(v.x, w0, acc.x); acc.y = fmaf(v.y, w0, acc.y);
        acc.z = fmaf(v.z, w0, acc.z); acc.w = fmaf(v.w, w0, acc.w);
    }

    // combine the two halves (lane i += lane i^16)
    acc.x += __shfl_xor_sync(0xffffffff, acc.x, 16);
    acc.y += __shfl_xor_sync(0xffffffff, acc.y, 16);
    acc.z += __shfl_xor_sync(0xffffffff, acc.z, 16);
    acc.w += __shfl_xor_sync(0xffffffff, acc.w, 16);

    if (half == 0) g_agg[node * IN_VEC + l16] = acc;
}

// Head: out = relu(agg @ W_gcn + b_gcn) @ W_lin + b_lin
// One thread per node. W_gcn in smem (32 KB), LDS.128 broadcast -> 4 FMA/load.
// (exact R8 scalar version — banked best)
__global__ __launch_bounds__(128)
void k_head(const float4* __restrict__ Wg4,
            const float* __restrict__ bg,
            const float* __restrict__ Wl,
            const float* __restrict__ bl,
            float2* __restrict__ out) {
    __shared__ float4 sW[IN_DIM * HID_VEC];   // 32 KB
    __shared__ float  sWl[HID_DIM * 2];
    __shared__ float  sbg[HID_DIM];

    int tid = threadIdx.x;
    for (int i = tid; i < IN_DIM * HID_VEC; i += blockDim.x) sW[i] = Wg4[i];
    for (int i = tid; i < HID_DIM * 2; i += blockDim.x) sWl[i] = Wl[i];
    for (int i = tid; i < HID_DIM; i += blockDim.x) sbg[i] = bg[i];
    __syncthreads();

    int node = blockIdx.x * blockDim.x + tid;
    if (node >= N_NODES) return;

    float a[IN_DIM];
    const float4* arow = &g_agg[node * IN_VEC];
#pragma unroll
    for (int k = 0; k < IN_VEC; k++) {
        float4 v = arow[k];
        a[4*k+0] = v.x; a[4*k+1] = v.y; a[4*k+2] = v.z; a[4*k+3] = v.w;
    }

    float o0 = bl[0], o1 = bl[1];
#pragma unroll 2
    for (int jq = 0; jq < HID_VEC; jq++) {
        float4 acc = make_float4(sbg[4*jq+0], sbg[4*jq+1],
                                 sbg[4*jq+2], sbg[4*jq+3]);
#pragma unroll
        for (int k = 0; k < IN_DIM; k++) {
            float4 w = sW[k * HID_VEC + jq];
            acc.x = fmaf(a[k], w.x, acc.x);
            acc.y = fmaf(a[k], w.y, acc.y);
            acc.z = fmaf(a[k], w.z, acc.z);
            acc.w = fmaf(a[k], w.w, acc.w);
        }
        acc.x = fmaxf(acc.x, 0.0f);
        acc.y = fmaxf(acc.y, 0.0f);
        acc.z = fmaxf(acc.z, 0.0f);
        acc.w = fmaxf(acc.w, 0.0f);
        int j = 4 * jq;
        o0 = fmaf(acc.x, sWl[2*(j+0)+0], o0);
        o1 = fmaf(acc.x, sWl[2*(j+0)+1], o1);
        o0 = fmaf(acc.y, sWl[2*(j+1)+0], o0);
        o1 = fmaf(acc.y, sWl[2*(j+1)+1], o1);
        o0 = fmaf(acc.z, sWl[2*(j+2)+0], o0);
        o1 = fmaf(acc.z, sWl[2*(j+2)+1], o1);
        o0 = fmaf(acc.w, sWl[2*(j+3)+0], o0);
        o1 = fmaf(acc.w, sWl[2*(j+3)+1], o1);
    }
    out[node] = make_float2(o0, o1);
}

// ---------------------------------------------------------------------------
extern "C" void kernel_launch(void* const* d_in, const int* in_sizes, int n_in,
                              void* d_out, int out_size) {
    const float* x  = (const float*)d_in[0];
    const int*   ei = (const int*)d_in[1];     // int32 (JAX default x64 off)
    const float* Wg = (const float*)d_in[2];
    const float* bg = (const float*)d_in[3];
    const float* Wl = (const float*)d_in[4];
    const float* bl = (const float*)d_in[5];
    float2*      out = (float2*)d_out;

    const float4* x4  = (const float4*)x;
    const float4* Wg4 = (const float4*)Wg;

    k_zero   <<<(N_NODES + 255) / 256, 256>>>();
    k_count  <<<(N_EDGES + 255) / 256, 256>>>(ei);
    k_scan1  <<<N_SCAN_BLOCKS, 256>>>();
    k_scan2  <<<1, 128>>>();
    k_scan3  <<<(N_NODES + 255) / 256, 256>>>();
    k_scatter<<<(N_EDGES + 255) / 256, 256>>>(ei);
    k_agg    <<<((N_NODES * 32) + 255) / 256, 256>>>(x4);
    k_head   <<<(N_NODES + 127) / 128, 128>>>(Wg4, bg, Wl, bl, out);
}

// round 14
// speedup vs baseline: 1.0440x; 1.0053x over previous
#include <cuda_runtime.h>
#include <cuda_fp16.h>

#define N_NODES 100000
#define N_EDGES 3200000
#define IN_DIM 64
#define HID_DIM 128
#define OUT_DIM 2
#define IN_VEC (IN_DIM / 4)       // 16 float4 per node row
#define HID_VEC (HID_DIM / 4)     // 32

#define SCAN_CHUNK 1024
#define N_SCAN_BLOCKS ((N_NODES + SCAN_CHUNK - 1) / SCAN_CHUNK)   // 98

// Scratch (device globals: allocation-free rule)
__device__ __align__(16) int    g_cnt[N_NODES];
__device__ __align__(16) int    g_start[N_NODES];
__device__ __align__(16) int    g_cur[N_NODES];
__device__ __align__(16) float  g_dinv[N_NODES];
__device__ __align__(16) int    g_bsum[N_SCAN_BLOCKS];
__device__ __align__(16) float2 g_entry[N_EDGES];          // {src bits, norm} 25.6 MB
__device__ __align__(16) uint2  g_xh[N_NODES * IN_VEC];    // fp16 mirror of x, 12.8 MB
__device__ __align__(16) float4 g_agg[N_NODES * IN_VEC];   // 25.6 MB

// ---------------------------------------------------------------------------
__global__ void k_zero() {
    int i = blockIdx.x * blockDim.x + threadIdx.x;
    if (i < N_NODES) g_cnt[i] = 0;
}

// fp16 mirror of x: each uint2 = 4 halfs = one float4 worth of columns
__global__ void k_half(const float4* __restrict__ x4) {
    int i = blockIdx.x * blockDim.x + threadIdx.x;
    if (i < N_NODES * IN_VEC) {
        float4 v = x4[i];
        __half2 h0 = __floats2half2_rn(v.x, v.y);
        __half2 h1 = __floats2half2_rn(v.z, v.w);
        uint2 u;
        u.x = *reinterpret_cast<unsigned*>(&h0);
        u.y = *reinterpret_cast<unsigned*>(&h1);
        g_xh[i] = u;
    }
}

// In-degree histogram (int reductions)
__global__ void k_count(const int* __restrict__ ei) {
    int i = blockIdx.x * blockDim.x + threadIdx.x;
    if (i < N_EDGES) {
        int d = ei[N_EDGES + i];
        if ((unsigned)d < N_NODES) atomicAdd(&g_cnt[d], 1);
    }
}

// Scan pass 1: per-block (1024 elems) exclusive scan of g_cnt into g_start,
// block totals to g_bsum. Also dinv = rsqrt(cnt+1) (self-loop incl).
__global__ __launch_bounds__(256)
void k_scan1() {
    __shared__ int s_sum[256];
    int b = blockIdx.x, t = threadIdx.x;
    int base = b * SCAN_CHUNK + t * 4;

    int c0 = 0, c1 = 0, c2 = 0, c3 = 0;
    if (base + 3 < N_NODES) {
        int4 c = *(const int4*)&g_cnt[base];
        c0 = c.x; c1 = c.y; c2 = c.z; c3 = c.w;
    } else {
        if (base + 0 < N_NODES) c0 = g_cnt[base + 0];
        if (base + 1 < N_NODES) c1 = g_cnt[base + 1];
        if (base + 2 < N_NODES) c2 = g_cnt[base + 2];
    }
    int s0 = c0, s1 = s0 + c1, s2 = s1 + c2, s3 = s2 + c3;
    s_sum[t] = s3;
    __syncthreads();
#pragma unroll
    for (int off = 1; off < 256; off <<= 1) {
        int v = 0;
        if (t >= off) v = s_sum[t - off];
        __syncthreads();
        if (t >= off) s_sum[t] += v;
        __syncthreads();
    }
    int excl = (t > 0) ? s_sum[t - 1] : 0;
    if (base + 0 < N_NODES) { g_start[base + 0] = excl;       g_dinv[base + 0] = rsqrtf((float)c0 + 1.0f); }
    if (base + 1 < N_NODES) { g_start[base + 1] = excl + s0;  g_dinv[base + 1] = rsqrtf((float)c1 + 1.0f); }
    if (base + 2 < N_NODES) { g_start[base + 2] = excl + s1;  g_dinv[base + 2] = rsqrtf((float)c2 + 1.0f); }
    if (base + 3 < N_NODES) { g_start[base + 3] = excl + s2;  g_dinv[base + 3] = rsqrtf((float)c3 + 1.0f); }
    if (t == 255) g_bsum[b] = s_sum[255];
}

// Scan pass 2: exclusive scan of the 98 block sums (single block)
__global__ __launch_bounds__(128)
void k_scan2() {
    __shared__ int s[128];
    int t = threadIdx.x;
    s[t] = (t < N_SCAN_BLOCKS) ? g_bsum[t] : 0;
    __syncthreads();
#pragma unroll
    for (int off = 1; off < 128; off <<= 1) {
        int v = 0;
        if (t >= off) v = s[t - off];
        __syncthreads();
        if (t >= off) s[t] += v;
        __syncthreads();
    }
    if (t < N_SCAN_BLOCKS) g_bsum[t] = (t > 0) ? s[t - 1] : 0;
}

// Scan pass 3: add block offsets; init write cursors
__global__ void k_scan3() {
    int i = blockIdx.x * blockDim.x + threadIdx.x;
    if (i < N_NODES) {
        int v = g_start[i] + g_bsum[i >> 10];
        g_start[i] = v;
        g_cur[i] = v;
    }
}

// Counting-sort fill: per-dst edge lists of packed {src, norm}
__global__ void k_scatter(const int* __restrict__ ei) {
    int i = blockIdx.x * blockDim.x + threadIdx.x;
    if (i < N_EDGES) {
        int s = ei[i];
        int t = ei[N_EDGES + i];
        if ((unsigned)s >= N_NODES || (unsigned)t >= N_NODES) return;
        float norm = g_dinv[s] * g_dinv[t];
        int slot = atomicAdd(&g_cur[t], 1);
        if ((unsigned)slot < N_EDGES)                 // clamp: corrupt -> wrong, not hang
            g_entry[slot] = make_float2(__int_as_float(s), norm);
    }
}

// Aggregate: 16 threads per node (R8 layout), fp16 gathers (128 B/edge),
// fp32 accumulation. Self-loop term uses exact fp32 x.
__global__ __launch_bounds__(256)
void k_agg(const float4* __restrict__ x4) {
    int gi = blockIdx.x * blockDim.x + threadIdx.x;
    if (gi >= N_NODES * IN_VEC) return;
    int node = gi >> 4;
    int lane = gi & 15;

    float di = g_dinv[node];
    float sl = di * di;
    float4 acc = x4[node * IN_VEC + lane];
    acc.x *= sl; acc.y *= sl; acc.z *= sl; acc.w *= sl;

    // Hard-clamped bounds: any upstream corruption ends finitely.
    int j = g_start[node];
    if (j < 0) j = 0;
    int cnt = g_cnt[node];
    if (cnt < 0) cnt = 0;
    long long e64 = (long long)j + cnt;
    int end = (e64 > N_EDGES) ? N_EDGES : (int)e64;

    for (; j + 1 < end; j += 2) {
        float2 en0 = g_entry[j];
        float2 en1 = g_entry[j + 1];
        int s0 = __float_as_int(en0.x);
        int s1 = __float_as_int(en1.x);
        if ((unsigned)s0 < N_NODES) {
            uint2 u = __ldg(&g_xh[s0 * IN_VEC + lane]);
            float2 f0 = __half22float2(*reinterpret_cast<__half2*>(&u.x));
            float2 f1 = __half22float2(*reinterpret_cast<__half2*>(&u.y));
            acc.x = fmaf(f0.x, en0.y, acc.x);
            acc.y = fmaf(f0.y, en0.y, acc.y);
            acc.z = fmaf(f1.x, en0.y, acc.z);
            acc.w = fmaf(f1.y, en0.y, acc.w);
        }
        if ((unsigned)s1 < N_NODES) {
            uint2 u = __ldg(&g_xh[s1 * IN_VEC + lane]);
            float2 f0 = __half22float2(*reinterpret_cast<__half2*>(&u.x));
            float2 f1 = __half22float2(*reinterpret_cast<__half2*>(&u.y));
            acc.x = fmaf(f0.x, en1.y, acc.x);
            acc.y = fmaf(f0.y, en1.y, acc.y);
            acc.z = fmaf(f1.x, en1.y, acc.z);
            acc.w = fmaf(f1.y, en1.y, acc.w);
        }
    }
    if (j < end) {
        float2 en = g_entry[j];
        int s0 = __float_as_int(en.x);
        if ((unsigned)s0 < N_NODES) {
            uint2 u = __ldg(&g_xh[s0 * IN_VEC + lane]);
            float2 f0 = __half22float2(*reinterpret_cast<__half2*>(&u.x));
            float2 f1 = __half22float2(*reinterpret_cast<__half2*>(&u.y));
            acc.x = fmaf(f0.x, en.y, acc.x);
            acc.y = fmaf(f0.y, en.y, acc.y);
            acc.z = fmaf(f1.x, en.y, acc.z);
            acc.w = fmaf(f1.y, en.y, acc.w);
        }
    }
    g_agg[node * IN_VEC + lane] = acc;
}

// Head: out = relu(agg @ W_gcn + b_gcn) @ W_lin + b_lin
// One thread per node. (exact R8 scalar version — banked best)
__global__ __launch_bounds__(128)
void k_head(const float4* __restrict__ Wg4,
            const float* __restrict__ bg,
            const float* __restrict__ Wl,
            const float* __restrict__ bl,
            float2* __restrict__ out) {
    __shared__ float4 sW[IN_DIM * HID_VEC];   // 32 KB
    __shared__ float  sWl[HID_DIM * 2];
    __shared__ float  sbg[HID_DIM];

    int tid = threadIdx.x;
    for (int i = tid; i < IN_DIM * HID_VEC; i += blockDim.x) sW[i] = Wg4[i];
    for (int i = tid; i < HID_DIM * 2; i += blockDim.x) sWl[i] = Wl[i];
    for (int i = tid; i < HID_DIM; i += blockDim.x) sbg[i] = bg[i];
    __syncthreads();

    int node = blockIdx.x * blockDim.x + tid;
    if (node >= N_NODES) return;

    float a[IN_DIM];
    const float4* arow = &g_agg[node * IN_VEC];
#pragma unroll
    for (int k = 0; k < IN_VEC; k++) {
        float4 v = arow[k];
        a[4*k+0] = v.x; a[4*k+1] = v.y; a[4*k+2] = v.z; a[4*k+3] = v.w;
    }

    float o0 = bl[0], o1 = bl[1];
#pragma unroll 2
    for (int jq = 0; jq < HID_VEC; jq++) {
        float4 acc = make_float4(sbg[4*jq+0], sbg[4*jq+1],
                                 sbg[4*jq+2], sbg[4*jq+3]);
#pragma unroll
        for (int k = 0; k < IN_DIM; k++) {
            float4 w = sW[k * HID_VEC + jq];
            acc.x = fmaf(a[k], w.x, acc.x);
            acc.y = fmaf(a[k], w.y, acc.y);
            acc.z = fmaf(a[k], w.z, acc.z);
            acc.w = fmaf(a[k], w.w, acc.w);
        }
        acc.x = fmaxf(acc.x, 0.0f);
        acc.y = fmaxf(acc.y, 0.0f);
        acc.z = fmaxf(acc.z, 0.0f);
        acc.w = fmaxf(acc.w, 0.0f);
        int j = 4 * jq;
        o0 = fmaf(acc.x, sWl[2*(j+0)+0], o0);
        o1 = fmaf(acc.x, sWl[2*(j+0)+1], o1);
        o0 = fmaf(acc.y, sWl[2*(j+1)+0], o0);
        o1 = fmaf(acc.y, sWl[2*(j+1)+1], o1);
        o0 = fmaf(acc.z, sWl[2*(j+2)+0], o0);
        o1 = fmaf(acc.z, sWl[2*(j+2)+1], o1);
        o0 = fmaf(acc.w, sWl[2*(j+3)+0], o0);
        o1 = fmaf(acc.w, sWl[2*(j+3)+1], o1);
    }
    out[node] = make_float2(o0, o1);
}

// ---------------------------------------------------------------------------
extern "C" void kernel_launch(void* const* d_in, const int* in_sizes, int n_in,
                              void* d_out, int out_size) {
    const float* x  = (const float*)d_in[0];
    const int*   ei = (const int*)d_in[1];     // int32 (JAX default x64 off)
    const float* Wg = (const float*)d_in[2];
    const float* bg = (const float*)d_in[3];
    const float* Wl = (const float*)d_in[4];
    const float* bl = (const float*)d_in[5];
    float2*      out = (float2*)d_out;

    const float4* x4  = (const float4*)x;
    const float4* Wg4 = (const float4*)Wg;

    k_zero   <<<(N_NODES + 255) / 256, 256>>>();
    k_half   <<<(N_NODES * IN_VEC + 255) / 256, 256>>>(x4);
    k_count  <<<(N_EDGES + 255) / 256, 256>>>(ei);
    k_scan1  <<<N_SCAN_BLOCKS, 256>>>();
    k_scan2  <<<1, 128>>>();
    k_scan3  <<<(N_NODES + 255) / 256, 256>>>();
    k_scatter<<<(N_EDGES + 255) / 256, 256>>>(ei);
    k_agg    <<<(N_NODES * IN_VEC + 255) / 256, 256>>>(x4);
    k_head   <<<(N_NODES + 127) / 128, 128>>>(Wg4, bg, Wl, bl, out);
}